// round 3
// baseline (speedup 1.0000x reference)
#include <cuda_runtime.h>

typedef unsigned long long ull;

// ---------------- problem constants ----------------
#define BATCH   128
#define HH      384
#define WW      384
#define OW      385          // output width/height for k=2 and k=4
#define SH      49           // output rows per strip
#define STRIPS  8            // ceil(385/49)
#define NPART   (STRIPS*BATCH)
#define NTHREADS 416         // 13 warps; threads 0..384 are "columns"

// smem: raw-row ring, 8 slots * 400 ull (packed x,y), + 65 floats reduction
#define RAW_STRIDE 400
#define SMEM_BYTES (8*RAW_STRIDE*8 + 65*4)

__device__ float g_part[NPART * 5];

// ---------------- packed f32x2 helpers ----------------
__device__ __forceinline__ ull f2pack(float lo, float hi) {
    ull r; asm("mov.b64 %0,{%1,%2};" : "=l"(r) : "f"(lo), "f"(hi)); return r;
}
__device__ __forceinline__ void f2unpack(ull v, float& lo, float& hi) {
    asm("mov.b64 {%0,%1},%2;" : "=f"(lo), "=f"(hi) : "l"(v));
}
__device__ __forceinline__ ull f2add(ull a, ull b) {
    ull r; asm("add.rn.f32x2 %0,%1,%2;" : "=l"(r) : "l"(a), "l"(b)); return r;
}
__device__ __forceinline__ ull f2mul(ull a, ull b) {
    ull r; asm("mul.rn.f32x2 %0,%1,%2;" : "=l"(r) : "l"(a), "l"(b)); return r;
}
__device__ __forceinline__ ull f2fma(ull a, ull b, ull c) {
    ull r; asm("fma.rn.f32x2 %0,%1,%2,%3;" : "=l"(r) : "l"(a), "l"(b), "l"(c)); return r;
}
#define F2NEG1 0xBF800000BF800000ULL   // (-1.0f, -1.0f)

// Scaled SSIM from raw window sums. n = k*k, c1 = C1*n^2, c2 = C2*n^2.
__device__ __forceinline__ float ssim_scaled(float Sx, float Sy, float Sxx, float Syy,
                                             float Sxy, float n, float c1, float c2)
{
    float t  = Sx * Sy;
    float A1 = fmaf(2.f, t, c1);                 // 2*Sx*Sy + C1*n^2
    float u  = fmaf(n, Sxy, -t);                 // n*Sxy - Sx*Sy
    float A2 = fmaf(2.f, u, c2);
    float p  = Sx * Sx;
    float pq = fmaf(Sy, Sy, p);                  // Sx^2 + Sy^2
    float B1 = pq + c1;
    float w  = fmaf(n, Sxx + Syy, -pq);          // n*(Sxx+Syy) - Sx^2 - Sy^2
    float B2 = w + c2;
    return __fdividef(A1 * A2, B1 * B2);
}

__global__ __launch_bounds__(NTHREADS, 1)
void msssim_main_kernel(const float* __restrict__ X,
                        const float* __restrict__ Y,
                        const float* __restrict__ DR)
{
    extern __shared__ ull sm8[];
    ull*   raw = sm8;                            // [8][RAW_STRIDE], col c at idx 4+c
    float* red = (float*)(sm8 + 8*RAW_STRIDE);   // 13 warps * 5

    const int tid = threadIdx.x;
    const int b   = blockIdx.y;
    const int i0  = blockIdx.x * SH;
    const int i1  = min(i0 + SH, OW);
    const int i1k = min(i1, HH);
    const int ibase = i0 - 6;
    const int M   = i1 - ibase;                  // 55 (or 48 for last strip)
    const int nOuter = (M + 7) >> 3;

    const float dr = DR[b];
    const float C1 = (0.01f * dr) * (0.01f * dr);
    const float C2 = (0.03f * dr) * (0.03f * dr);
    const float c1_2 = C1 * 16.f,   c2_2 = C2 * 16.f;     // n=4
    const float c1_4 = C1 * 256.f,  c2_4 = C2 * 256.f;    // n=16
    const float c1_7 = C1 * 2401.f, c2_7 = C2 * 2401.f;   // n=49

    // zero horizontal pad cells (idx 0..3 and 388..391) of all 8 slots
    if (tid < 64) {
        int s = tid >> 3, c = tid & 7;
        int idx = (c < 4) ? c : (c + 384);
        raw[s * RAW_STRIDE + idx] = 0ULL;
    }

    // ---- register-resident h-sum rings (constant-indexed after unroll) ----
    ull h7s[8], h7q[8]; float h7xy[8];
    ull h4s[4], h4q[4]; float h4xy[4];
    ull h2s[2], h2q[2]; float h2xy[2];
    #pragma unroll
    for (int q = 0; q < 8; ++q) { h7s[q] = 0; h7q[q] = 0; h7xy[q] = 0.f; }
    #pragma unroll
    for (int q = 0; q < 4; ++q) { h4s[q] = 0; h4q[q] = 0; h4xy[q] = 0.f; }
    #pragma unroll
    for (int q = 0; q < 2; ++q) { h2s[q] = 0; h2q[q] = 0; h2xy[q] = 0.f; }

    ull v7s = 0, v7q = 0; float v7xy = 0.f;
    float acc1 = 0.f, acc2 = 0.f, acc4 = 0.f, acc7 = 0.f, accL = 0.f;

    const size_t base = (size_t)b * (HH * WW);
    const int  j       = tid;
    const bool colMain = (tid < 384);
    const bool colExt  = (tid <= 384);

    // prologue: prefetch row r = ibase+3 = i0-3
    float xcur = 0.f, ycur = 0.f;
    {
        int rp = i0 - 3;
        if (colMain && (unsigned)rp < HH) {
            size_t o = base + (size_t)rp * WW + j;
            xcur = X[o]; ycur = Y[o];
        }
    }

    for (int mo = 0; mo < nOuter; ++mo) {
        #pragma unroll
        for (int u = 0; u < 8; ++u) {
            const int m = (mo << 3) + u;
            if (m < M) {
                const int i = ibase + m;
                const int r = i + 3;
                const bool rval = ((unsigned)r < HH);

                // prefetch row r+1 (consumed next iteration)
                float xn = 0.f, yn = 0.f;
                if (colMain && (unsigned)(r + 1) < HH) {
                    size_t o = base + (size_t)(r + 1) * WW + j;
                    xn = X[o]; yn = Y[o];
                }

                // store raw row r into ring slot u
                if (colMain && rval)
                    raw[u * RAW_STRIDE + 4 + j] = f2pack(xcur, ycur);
                __syncthreads();

                // k=1 SSIM for row r
                if (colMain && rval && r >= i0 && r < i1k) {
                    float t  = xcur * ycur;
                    float a1 = fmaf(2.f, t, C1);
                    float b1 = fmaf(xcur, xcur, fmaf(ycur, ycur, C1));
                    acc1 += __fdividef(a1, b1);
                }

                // ---- h7 for row r (raw slot u) -> ring slot u ----
                if (rval && colExt) {
                    const ull* rb = raw + u * RAW_STRIDE + (j + 1);
                    ull p0 = rb[0], p1 = rb[1], p2 = rb[2], p3 = rb[3],
                        p4 = rb[4], p5 = rb[5], p6 = rb[6];
                    float x0,y0,x1,y1,x2,y2,x3,y3,x4,y4,x5,y5,x6,y6;
                    f2unpack(p0,x0,y0); f2unpack(p1,x1,y1); f2unpack(p2,x2,y2);
                    f2unpack(p3,x3,y3); f2unpack(p4,x4,y4); f2unpack(p5,x5,y5);
                    f2unpack(p6,x6,y6);
                    h7s[u]  = f2add(f2add(f2add(p0,p1),f2add(p2,p3)),
                                    f2add(f2add(p4,p5),p6));
                    h7q[u]  = f2fma(p0,p0, f2fma(p1,p1, f2fma(p2,p2,
                              f2fma(p3,p3, f2fma(p4,p4, f2fma(p5,p5, f2mul(p6,p6)))))));
                    h7xy[u] = fmaf(x0,y0, fmaf(x1,y1, fmaf(x2,y2,
                              fmaf(x3,y3, fmaf(x4,y4, fmaf(x5,y5, x6*y6))))));
                } else {
                    h7s[u] = 0; h7q[u] = 0; h7xy[u] = 0.f;
                }
                // v7 running: add row r, subtract row i-4 (stored 7 iters ago)
                v7s = f2add(v7s, h7s[u]);
                v7q = f2add(v7q, h7q[u]);
                v7xy += h7xy[u];
                v7s = f2fma(h7s[(u+1)&7], F2NEG1, v7s);
                v7q = f2fma(h7q[(u+1)&7], F2NEG1, v7q);
                v7xy -= h7xy[(u+1)&7];

                // ---- h4 for row i+1 = r-2 (raw slot (u+6)&7) -> ring slot u&3 ----
                if (((unsigned)(r - 2) < HH) && colExt) {
                    const ull* rb = raw + ((u+6)&7) * RAW_STRIDE + (j + 2);
                    ull p0 = rb[0], p1 = rb[1], p2 = rb[2], p3 = rb[3];
                    float x0,y0,x1,y1,x2,y2,x3,y3;
                    f2unpack(p0,x0,y0); f2unpack(p1,x1,y1);
                    f2unpack(p2,x2,y2); f2unpack(p3,x3,y3);
                    h4s[u&3]  = f2add(f2add(p0,p1), f2add(p2,p3));
                    h4q[u&3]  = f2fma(p0,p0, f2fma(p1,p1, f2fma(p2,p2, f2mul(p3,p3))));
                    h4xy[u&3] = fmaf(x0,y0, fmaf(x1,y1, fmaf(x2,y2, x3*y3)));
                } else {
                    h4s[u&3] = 0; h4q[u&3] = 0; h4xy[u&3] = 0.f;
                }

                // ---- h2 for row i = r-3 (raw slot (u+5)&7) -> ring slot u&1 ----
                if (((unsigned)(r - 3) < HH) && colExt) {
                    const ull* rb = raw + ((u+5)&7) * RAW_STRIDE + (j + 3);
                    ull p0 = rb[0], p1 = rb[1];
                    float x0,y0,x1,y1;
                    f2unpack(p0,x0,y0); f2unpack(p1,x1,y1);
                    h2s[u&1]  = f2add(p0,p1);
                    h2q[u&1]  = f2fma(p0,p0, f2mul(p1,p1));
                    h2xy[u&1] = fmaf(x0,y0, x1*y1);
                } else {
                    h2s[u&1] = 0; h2q[u&1] = 0; h2xy[u&1] = 0.f;
                }

                // -------- emit output row i --------
                if (i >= i0 && colExt) {
                    float Sx, Sy, Sxx, Syy;
                    // v2 = resum of 2 ring slots
                    ull  s = f2add(h2s[0], h2s[1]);
                    ull  qq = f2add(h2q[0], h2q[1]);
                    float xy = h2xy[0] + h2xy[1];
                    f2unpack(s, Sx, Sy); f2unpack(qq, Sxx, Syy);
                    acc2 += ssim_scaled(Sx, Sy, Sxx, Syy, xy, 4.f, c1_2, c2_2);
                    // v4 = resum of 4 ring slots
                    s  = f2add(f2add(h4s[0], h4s[1]), f2add(h4s[2], h4s[3]));
                    qq = f2add(f2add(h4q[0], h4q[1]), f2add(h4q[2], h4q[3]));
                    xy = (h4xy[0] + h4xy[1]) + (h4xy[2] + h4xy[3]);
                    f2unpack(s, Sx, Sy); f2unpack(qq, Sxx, Syy);
                    acc4 += ssim_scaled(Sx, Sy, Sxx, Syy, xy, 16.f, c1_4, c2_4);
                    if (colMain && i < HH) {
                        f2unpack(v7s, Sx, Sy); f2unpack(v7q, Sxx, Syy);
                        acc7 += ssim_scaled(Sx, Sy, Sxx, Syy, v7xy, 49.f, c1_7, c2_7);
                        accL += fabsf(Sx - Sy);   // 49 * |box7(X)-box7(Y)|
                    }
                }

                xcur = xn; ycur = yn;
            }
        }
    }

    // ---------------- deterministic block reduction ----------------
    #pragma unroll
    for (int o = 16; o > 0; o >>= 1) {
        acc1 += __shfl_down_sync(0xFFFFFFFFu, acc1, o);
        acc2 += __shfl_down_sync(0xFFFFFFFFu, acc2, o);
        acc4 += __shfl_down_sync(0xFFFFFFFFu, acc4, o);
        acc7 += __shfl_down_sync(0xFFFFFFFFu, acc7, o);
        accL += __shfl_down_sync(0xFFFFFFFFu, accL, o);
    }
    __syncthreads();
    const int w = tid >> 5, lane = tid & 31;
    if (lane == 0) {
        red[w*5 + 0] = acc1; red[w*5 + 1] = acc2; red[w*5 + 2] = acc4;
        red[w*5 + 3] = acc7; red[w*5 + 4] = accL;
    }
    __syncthreads();
    if (tid == 0) {
        float s0 = 0.f, s1 = 0.f, s2 = 0.f, s3 = 0.f, s4 = 0.f;
        for (int ww = 0; ww < 13; ++ww) {
            s0 += red[ww*5 + 0]; s1 += red[ww*5 + 1]; s2 += red[ww*5 + 2];
            s3 += red[ww*5 + 3]; s4 += red[ww*5 + 4];
        }
        const int pb = (b * STRIPS + blockIdx.x) * 5;
        g_part[pb + 0] = s0; g_part[pb + 1] = s1; g_part[pb + 2] = s2;
        g_part[pb + 3] = s3; g_part[pb + 4] = s4;
    }
}

__global__ void msssim_reduce_kernel(float* __restrict__ out)
{
    __shared__ double red[256][5];
    double a0 = 0, a1 = 0, a2 = 0, a3 = 0, a4 = 0;
    for (int idx = threadIdx.x; idx < NPART; idx += 256) {
        a0 += (double)g_part[idx*5 + 0];
        a1 += (double)g_part[idx*5 + 1];
        a2 += (double)g_part[idx*5 + 2];
        a3 += (double)g_part[idx*5 + 3];
        a4 += (double)g_part[idx*5 + 4];
    }
    red[threadIdx.x][0] = a0; red[threadIdx.x][1] = a1; red[threadIdx.x][2] = a2;
    red[threadIdx.x][3] = a3; red[threadIdx.x][4] = a4;
    __syncthreads();
    for (int s = 128; s > 0; s >>= 1) {
        if (threadIdx.x < s) {
            #pragma unroll
            for (int q = 0; q < 5; ++q) red[threadIdx.x][q] += red[threadIdx.x + s][q];
        }
        __syncthreads();
    }
    if (threadIdx.x == 0) {
        const double n384 = (double)BATCH * 384.0 * 384.0;
        const double n385 = (double)BATCH * 385.0 * 385.0;
        double m1 = red[0][0] / n384;
        double m2 = red[0][1] / n385;
        double m4 = red[0][2] / n385;
        double m7 = red[0][3] / n384;
        double l1 = red[0][4] / (49.0 * n384);
        double loss = 0.84 * (1.0 - m1 * m2 * m4 * m7) + 0.16 * l1;
        out[0] = (float)loss;
    }
}

extern "C" void kernel_launch(void* const* d_in, const int* in_sizes, int n_in,
                              void* d_out, int out_size)
{
    (void)in_sizes; (void)n_in; (void)out_size;
    const float* X  = (const float*)d_in[0];
    const float* Y  = (const float*)d_in[1];
    const float* DR = (const float*)d_in[2];

    cudaFuncSetAttribute(msssim_main_kernel,
                         cudaFuncAttributeMaxDynamicSharedMemorySize, SMEM_BYTES);

    dim3 grid(STRIPS, BATCH);
    msssim_main_kernel<<<grid, NTHREADS, SMEM_BYTES>>>(X, Y, DR);
    msssim_reduce_kernel<<<1, 256>>>((float*)d_out);
}

// round 4
// speedup vs baseline: 1.4906x; 1.4906x over previous
#include <cuda_runtime.h>

typedef unsigned long long ull;

// ---------------- problem constants ----------------
#define BATCH   128
#define HH      384
#define WW      384
#define OW      385          // output width/height for k=2 and k=4
#define SH      49           // output rows per strip
#define STRIPS  8            // ceil(385/49)
#define NPART   (STRIPS*BATCH)
#define NTHREADS 416         // 13 warps; threads 0..384 are "columns"

// ---------------- shared layout (ull units) ----------------
// raw ring:  8 slots * 400 ull (packed x,y), col c at idx 4+c     [0, 3200)
// r7sq ring: 8 slots * 385 ulonglong2 (s,q)                       [3200, 9360)
// r7xy ring: 8 slots * 385 float  (= 1540 ull)                    [9360, 10900)
// red:       65 floats                                            [10900, +33)
#define RAW_ULL    3200
#define SQ_ULL     6160
#define XY_ULL     1540
#define ZERO_ULL   (RAW_ULL + SQ_ULL + XY_ULL)          // 10900
#define SMEM_BYTES ((ZERO_ULL + 33) * 8)

__device__ float g_part[NPART * 5];

// ---------------- packed f32x2 helpers ----------------
__device__ __forceinline__ ull f2pack(float lo, float hi) {
    ull r; asm("mov.b64 %0,{%1,%2};" : "=l"(r) : "f"(lo), "f"(hi)); return r;
}
__device__ __forceinline__ void f2unpack(ull v, float& lo, float& hi) {
    asm("mov.b64 {%0,%1},%2;" : "=f"(lo), "=f"(hi) : "l"(v));
}
__device__ __forceinline__ ull f2add(ull a, ull b) {
    ull r; asm("add.rn.f32x2 %0,%1,%2;" : "=l"(r) : "l"(a), "l"(b)); return r;
}
__device__ __forceinline__ ull f2mul(ull a, ull b) {
    ull r; asm("mul.rn.f32x2 %0,%1,%2;" : "=l"(r) : "l"(a), "l"(b)); return r;
}
__device__ __forceinline__ ull f2fma(ull a, ull b, ull c) {
    ull r; asm("fma.rn.f32x2 %0,%1,%2,%3;" : "=l"(r) : "l"(a), "l"(b), "l"(c)); return r;
}
#define F2NEG1 0xBF800000BF800000ULL   // (-1.0f, -1.0f)

// Scaled SSIM from raw window sums. n = k*k, c1 = C1*n^2, c2 = C2*n^2.
__device__ __forceinline__ float ssim_scaled(float Sx, float Sy, float Sxx, float Syy,
                                             float Sxy, float n, float c1, float c2)
{
    float t  = Sx * Sy;
    float A1 = fmaf(2.f, t, c1);
    float u  = fmaf(n, Sxy, -t);
    float A2 = fmaf(2.f, u, c2);
    float p  = Sx * Sx;
    float pq = fmaf(Sy, Sy, p);
    float B1 = pq + c1;
    float w  = fmaf(n, Sxx + Syy, -pq);
    float B2 = w + c2;
    return __fdividef(A1 * A2, B1 * B2);
}

__global__ __launch_bounds__(NTHREADS, 1)
void msssim_main_kernel(const float* __restrict__ X,
                        const float* __restrict__ Y,
                        const float* __restrict__ DR)
{
    extern __shared__ ull sm8[];
    ull*         raw  = sm8;                                  // [8][400]
    ulonglong2*  r7sq = (ulonglong2*)(sm8 + RAW_ULL);         // [8][385]
    float*       r7xy = (float*)(sm8 + RAW_ULL + SQ_ULL);     // [8][385]
    float*       red  = (float*)(sm8 + ZERO_ULL);             // 13*5

    const int tid = threadIdx.x;
    const int b   = blockIdx.y;
    const int i0  = blockIdx.x * SH;
    const int i1  = min(i0 + SH, OW);
    const int i1k = min(i1, HH);
    const int ibase = i0 - 6;
    const int M   = i1 - ibase;                 // 55 (48 for last strip)
    const int MP  = (M + 3) & ~3;               // 56 / 48
    const int nPairs = MP >> 1;

    const float dr = DR[b];
    const float C1 = (0.01f * dr) * (0.01f * dr);
    const float C2 = (0.03f * dr) * (0.03f * dr);
    const float c1_2 = C1 * 16.f,   c2_2 = C2 * 16.f;
    const float c1_4 = C1 * 256.f,  c2_4 = C2 * 256.f;
    const float c1_7 = C1 * 2401.f, c2_7 = C2 * 2401.f;

    // zero ALL ring smem (reads outside the image then yield clean zeros)
    for (int k = tid; k < ZERO_ULL; k += NTHREADS) sm8[k] = 0ULL;

    // register rings (compile-time indexed after unroll)
    ull h4s[4], h4q[4]; float h4xy[4];
    ull h2s[2], h2q[2]; float h2xy[2];
    #pragma unroll
    for (int q = 0; q < 4; ++q) { h4s[q] = 0; h4q[q] = 0; h4xy[q] = 0.f; }
    #pragma unroll
    for (int q = 0; q < 2; ++q) { h2s[q] = 0; h2q[q] = 0; h2xy[q] = 0.f; }

    ull v7s = 0, v7q = 0; float v7xy = 0.f;
    float acc1 = 0.f, acc2 = 0.f, acc4 = 0.f, acc7 = 0.f, accL = 0.f;

    const size_t base = (size_t)b * (HH * WW);
    const int  j       = tid;
    const bool colMain = (tid < 384);
    const bool colExt  = (tid <= 384);

    // prologue: prefetch rows ibase+3, ibase+4 (first pair's rows)
    float xA = 0.f, yA = 0.f, xB = 0.f, yB = 0.f;
    if (colMain) {
        int rA = ibase + 3;
        if ((unsigned)rA < HH) {
            size_t o = base + (size_t)rA * WW + j;
            xA = X[o]; yA = Y[o];
        }
        if ((unsigned)(rA + 1) < HH) {
            size_t o = base + (size_t)(rA + 1) * WW + j;
            xB = X[o]; yB = Y[o];
        }
    }
    __syncthreads();    // zero-init complete before first raw stores

    for (int mp = 0; mp < nPairs; ++mp) {
        #pragma unroll
        for (int up = 0; up < 2; ++up) {
            if ((mp & 1) == up) continue;       // never taken; keeps up compile-time
        }
        // we unroll pairs two at a time so body index t = m&3 is compile-time
        ;
    }

    // main loop: outer over groups of 4 rows; inner unrolled pairs
    const int nQuad = MP >> 2;
    for (int mo = 0; mo < nQuad; ++mo) {
        #pragma unroll
        for (int up = 0; up < 2; ++up) {
            const int m0 = (mo << 2) + (up << 1);   // body indices m0, m0+1
            // prefetch rows for next pair (rows ibase+m0+5, +6)
            float xpa = 0.f, ypa = 0.f, xpb = 0.f, ypb = 0.f;
            if (colMain) {
                int rn = ibase + m0 + 5;
                if ((unsigned)rn < HH) {
                    size_t o = base + (size_t)rn * WW + j;
                    xpa = X[o]; ypa = Y[o];
                }
                if ((unsigned)(rn + 1) < HH) {
                    size_t o = base + (size_t)(rn + 1) * WW + j;
                    xpb = X[o]; ypb = Y[o];
                }
            }
            // store the two current rows (zeros for invalid rows keep rings clean)
            if (colMain) {
                raw[(m0 & 7) * 400 + 4 + j]       = f2pack(xA, yA);
                raw[((m0 + 1) & 7) * 400 + 4 + j] = f2pack(xB, yB);
            }
            __syncthreads();

            #pragma unroll
            for (int s = 0; s < 2; ++s) {
                const int m = m0 + s;
                const int t = (up << 1) + s;        // m & 3, compile-time
                const int i = ibase + m;
                const int r = i + 3;
                const float xc = s ? xB : xA;
                const float yc = s ? yB : yA;

                // ---- k=1 SSIM for row r ----
                if (colMain && r >= i0 && r < i1k) {
                    float tt = xc * yc;
                    float a1 = fmaf(2.f, tt, C1);
                    float b1 = fmaf(xc, xc, fmaf(yc, yc, C1));
                    acc1 += __fdividef(a1, b1);
                }

                // ---- h7 for row r (raw slot m&7) ----
                {
                    const ull* rb = raw + (m & 7) * 400 + (j + 1);
                    ull p0 = rb[0], p1 = rb[1], p2 = rb[2], p3 = rb[3],
                        p4 = rb[4], p5 = rb[5], p6 = rb[6];
                    float x0,y0,x1,y1,x2,y2,x3,y3,x4,y4,x5,y5,x6,y6;
                    f2unpack(p0,x0,y0); f2unpack(p1,x1,y1); f2unpack(p2,x2,y2);
                    f2unpack(p3,x3,y3); f2unpack(p4,x4,y4); f2unpack(p5,x5,y5);
                    f2unpack(p6,x6,y6);
                    ull  s7 = f2add(f2add(f2add(p0,p1),f2add(p2,p3)),
                                    f2add(f2add(p4,p5),p6));
                    ull  q7 = f2fma(p0,p0, f2fma(p1,p1, f2fma(p2,p2,
                              f2fma(p3,p3, f2fma(p4,p4, f2fma(p5,p5, f2mul(p6,p6)))))));
                    float w7 = fmaf(x0,y0, fmaf(x1,y1, fmaf(x2,y2,
                               fmaf(x3,y3, fmaf(x4,y4, fmaf(x5,y5, x6*y6))))));
                    v7s = f2add(v7s, s7); v7q = f2add(v7q, q7); v7xy += w7;
                    if (colExt) {
                        const int so = ((m + 1) & 7) * 385 + j;   // row i-4 (or zeros)
                        ulonglong2 osq = r7sq[so];
                        float      oxy = r7xy[so];
                        const int sn = (m & 7) * 385 + j;
                        ulonglong2 nsq; nsq.x = s7; nsq.y = q7;
                        r7sq[sn] = nsq; r7xy[sn] = w7;
                        v7s = f2fma(osq.x, F2NEG1, v7s);
                        v7q = f2fma(osq.y, F2NEG1, v7q);
                        v7xy -= oxy;
                    }
                }

                // ---- h4 for row i+1 = r-2 (raw slot (m+6)&7) -> reg slot t ----
                {
                    const ull* rb = raw + ((m + 6) & 7) * 400 + (j + 2);
                    ull p0 = rb[0], p1 = rb[1], p2 = rb[2], p3 = rb[3];
                    float x0,y0,x1,y1,x2,y2,x3,y3;
                    f2unpack(p0,x0,y0); f2unpack(p1,x1,y1);
                    f2unpack(p2,x2,y2); f2unpack(p3,x3,y3);
                    h4s[t]  = f2add(f2add(p0,p1), f2add(p2,p3));
                    h4q[t]  = f2fma(p0,p0, f2fma(p1,p1, f2fma(p2,p2, f2mul(p3,p3))));
                    h4xy[t] = fmaf(x0,y0, fmaf(x1,y1, fmaf(x2,y2, x3*y3)));
                }

                // ---- h2 for row i = r-3 (raw slot (m+5)&7) -> reg slot t&1 ----
                {
                    const ull* rb = raw + ((m + 5) & 7) * 400 + (j + 3);
                    ull p0 = rb[0], p1 = rb[1];
                    float x0,y0,x1,y1;
                    f2unpack(p0,x0,y0); f2unpack(p1,x1,y1);
                    h2s[t & 1]  = f2add(p0, p1);
                    h2q[t & 1]  = f2fma(p0,p0, f2mul(p1,p1));
                    h2xy[t & 1] = fmaf(x0,y0, x1*y1);
                }

                // ---- emit output row i ----
                if (i >= i0 && i < i1 && colExt) {
                    float Sx, Sy, Sxx, Syy;
                    ull  ss = f2add(h2s[0], h2s[1]);
                    ull  qq = f2add(h2q[0], h2q[1]);
                    float xy = h2xy[0] + h2xy[1];
                    f2unpack(ss, Sx, Sy); f2unpack(qq, Sxx, Syy);
                    acc2 += ssim_scaled(Sx, Sy, Sxx, Syy, xy, 4.f, c1_2, c2_2);
                    ss = f2add(f2add(h4s[0], h4s[1]), f2add(h4s[2], h4s[3]));
                    qq = f2add(f2add(h4q[0], h4q[1]), f2add(h4q[2], h4q[3]));
                    xy = (h4xy[0] + h4xy[1]) + (h4xy[2] + h4xy[3]);
                    f2unpack(ss, Sx, Sy); f2unpack(qq, Sxx, Syy);
                    acc4 += ssim_scaled(Sx, Sy, Sxx, Syy, xy, 16.f, c1_4, c2_4);
                    if (colMain && i < HH) {
                        f2unpack(v7s, Sx, Sy); f2unpack(v7q, Sxx, Syy);
                        acc7 += ssim_scaled(Sx, Sy, Sxx, Syy, v7xy, 49.f, c1_7, c2_7);
                        accL += fabsf(Sx - Sy);
                    }
                }
            }
            xA = xpa; yA = ypa; xB = xpb; yB = ypb;
        }
    }

    // ---------------- deterministic block reduction ----------------
    #pragma unroll
    for (int o = 16; o > 0; o >>= 1) {
        acc1 += __shfl_down_sync(0xFFFFFFFFu, acc1, o);
        acc2 += __shfl_down_sync(0xFFFFFFFFu, acc2, o);
        acc4 += __shfl_down_sync(0xFFFFFFFFu, acc4, o);
        acc7 += __shfl_down_sync(0xFFFFFFFFu, acc7, o);
        accL += __shfl_down_sync(0xFFFFFFFFu, accL, o);
    }
    __syncthreads();
    const int w = tid >> 5, lane = tid & 31;
    if (lane == 0) {
        red[w*5 + 0] = acc1; red[w*5 + 1] = acc2; red[w*5 + 2] = acc4;
        red[w*5 + 3] = acc7; red[w*5 + 4] = accL;
    }
    __syncthreads();
    if (tid == 0) {
        float s0 = 0.f, s1 = 0.f, s2 = 0.f, s3 = 0.f, s4 = 0.f;
        for (int ww = 0; ww < 13; ++ww) {
            s0 += red[ww*5 + 0]; s1 += red[ww*5 + 1]; s2 += red[ww*5 + 2];
            s3 += red[ww*5 + 3]; s4 += red[ww*5 + 4];
        }
        const int pb = (b * STRIPS + blockIdx.x) * 5;
        g_part[pb + 0] = s0; g_part[pb + 1] = s1; g_part[pb + 2] = s2;
        g_part[pb + 3] = s3; g_part[pb + 4] = s4;
    }
}

__global__ void msssim_reduce_kernel(float* __restrict__ out)
{
    __shared__ double red[256][5];
    double a0 = 0, a1 = 0, a2 = 0, a3 = 0, a4 = 0;
    for (int idx = threadIdx.x; idx < NPART; idx += 256) {
        a0 += (double)g_part[idx*5 + 0];
        a1 += (double)g_part[idx*5 + 1];
        a2 += (double)g_part[idx*5 + 2];
        a3 += (double)g_part[idx*5 + 3];
        a4 += (double)g_part[idx*5 + 4];
    }
    red[threadIdx.x][0] = a0; red[threadIdx.x][1] = a1; red[threadIdx.x][2] = a2;
    red[threadIdx.x][3] = a3; red[threadIdx.x][4] = a4;
    __syncthreads();
    for (int s = 128; s > 0; s >>= 1) {
        if (threadIdx.x < s) {
            #pragma unroll
            for (int q = 0; q < 5; ++q) red[threadIdx.x][q] += red[threadIdx.x + s][q];
        }
        __syncthreads();
    }
    if (threadIdx.x == 0) {
        const double n384 = (double)BATCH * 384.0 * 384.0;
        const double n385 = (double)BATCH * 385.0 * 385.0;
        double m1 = red[0][0] / n384;
        double m2 = red[0][1] / n385;
        double m4 = red[0][2] / n385;
        double m7 = red[0][3] / n384;
        double l1 = red[0][4] / (49.0 * n384);
        double loss = 0.84 * (1.0 - m1 * m2 * m4 * m7) + 0.16 * l1;
        out[0] = (float)loss;
    }
}

// phase-shift helper so ncu's "-s 5 -c 1" lands on the MAIN kernel (period 5)
__global__ void msssim_noop_kernel() {}

extern "C" void kernel_launch(void* const* d_in, const int* in_sizes, int n_in,
                              void* d_out, int out_size)
{
    (void)in_sizes; (void)n_in; (void)out_size;
    const float* X  = (const float*)d_in[0];
    const float* Y  = (const float*)d_in[1];
    const float* DR = (const float*)d_in[2];

    cudaFuncSetAttribute(msssim_main_kernel,
                         cudaFuncAttributeMaxDynamicSharedMemorySize, SMEM_BYTES);

    dim3 grid(STRIPS, BATCH);
    msssim_main_kernel<<<grid, NTHREADS, SMEM_BYTES>>>(X, Y, DR);
    msssim_reduce_kernel<<<1, 256>>>((float*)d_out);
    msssim_noop_kernel<<<1, 32>>>();
    msssim_noop_kernel<<<1, 32>>>();
    msssim_noop_kernel<<<1, 32>>>();
}

// round 5
// speedup vs baseline: 1.9975x; 1.3401x over previous
#include <cuda_runtime.h>

typedef unsigned long long ull;

// ---------------- problem constants ----------------
#define BATCH   128
#define HH      384
#define WW      384
#define OW      385
#define SH      49
#define STRIPS  8
#define NPART   (STRIPS*BATCH)
#define NTHREADS 224        // 7 warps; thread t owns cols 2t, 2t+1 (t<193)

// ---------------- shared layout (ull units) ----------------
// raw ring : [0,3200)     8 slots * 400 ull. Per slot: E half [0,200): col 2u at u+2;
//                         O half [200,400): col 2u+1 at 200+u+2. Pads stay zero.
// r7sq ring: [3200,9600)  ulonglong2[8*400]: slot*400 + t (col j0) / +200+t (col j1)
// r7xy ring: [9600,11200) float[8*400]
// red      : [11200,+18)  35 floats
#define ZERO_ULL   11200
#define SMEM_BYTES ((ZERO_ULL + 18) * 8)

__device__ float g_part[NPART * 5];

// ---------------- packed f32x2 helpers ----------------
__device__ __forceinline__ ull f2pack(float lo, float hi) {
    ull r; asm("mov.b64 %0,{%1,%2};" : "=l"(r) : "f"(lo), "f"(hi)); return r;
}
__device__ __forceinline__ void f2unpack(ull v, float& lo, float& hi) {
    asm("mov.b64 {%0,%1},%2;" : "=f"(lo), "=f"(hi) : "l"(v));
}
__device__ __forceinline__ ull f2add(ull a, ull b) {
    ull r; asm("add.rn.f32x2 %0,%1,%2;" : "=l"(r) : "l"(a), "l"(b)); return r;
}
__device__ __forceinline__ ull f2mul(ull a, ull b) {
    ull r; asm("mul.rn.f32x2 %0,%1,%2;" : "=l"(r) : "l"(a), "l"(b)); return r;
}
__device__ __forceinline__ ull f2fma(ull a, ull b, ull c) {
    ull r; asm("fma.rn.f32x2 %0,%1,%2,%3;" : "=l"(r) : "l"(a), "l"(b), "l"(c)); return r;
}
#define F2NEG1 0xBF800000BF800000ULL   // (-1.0f, -1.0f)

__device__ __forceinline__ float ssim_scaled(float Sx, float Sy, float Sxx, float Syy,
                                             float Sxy, float n, float c1, float c2)
{
    float t  = Sx * Sy;
    float A1 = fmaf(2.f, t, c1);
    float u  = fmaf(n, Sxy, -t);
    float A2 = fmaf(2.f, u, c2);
    float p  = Sx * Sx;
    float pq = fmaf(Sy, Sy, p);
    float B1 = pq + c1;
    float w  = fmaf(n, Sxx + Syy, -pq);
    float B2 = w + c2;
    return __fdividef(A1 * A2, B1 * B2);
}

__global__ __launch_bounds__(NTHREADS, 2)
void msssim_main_kernel(const float* __restrict__ X,
                        const float* __restrict__ Y,
                        const float* __restrict__ DR)
{
    extern __shared__ ull sm8[];
    ull*         raw  = sm8;
    ulonglong2*  r7sq = (ulonglong2*)(sm8 + 3200);
    float*       r7xy = (float*)(sm8 + 9600);
    float*       red  = (float*)(sm8 + ZERO_ULL);

    const int tid = threadIdx.x;
    const int b   = blockIdx.y;
    const int i0  = blockIdx.x * SH;
    const int i1  = min(i0 + SH, OW);
    const int i1k = min(i1, HH);
    const int ibase = i0 - 6;
    const int M   = i1 - ibase;                 // 55 (48 last strip)
    const int MP  = (M + 3) & ~3;
    const int nQuad = MP >> 2;

    const float dr = DR[b];
    const float C1 = (0.01f * dr) * (0.01f * dr);
    const float C2 = (0.03f * dr) * (0.03f * dr);
    const float c1_2 = C1 * 16.f,   c2_2 = C2 * 16.f;
    const float c1_4 = C1 * 256.f,  c2_4 = C2 * 256.f;
    const float c1_7 = C1 * 2401.f, c2_7 = C2 * 2401.f;

    // zero all ring smem (reads outside image yield clean zeros)
    for (int k = tid; k < ZERO_ULL; k += NTHREADS) sm8[k] = 0ULL;

    const int  t    = tid;
    const bool act  = (t < 193);    // owns output col j0 = 2t (<= 384)
    const bool full = (t < 192);    // j0,j1 both real input cols

    // register rings, 2 cols (suffix 0 = col 2t, 1 = col 2t+1)
    ull h4s0[4], h4q0[4], h4s1[4], h4q1[4]; float h4xy0[4], h4xy1[4];
    ull h2s0[2], h2q0[2], h2s1[2], h2q1[2]; float h2xy0[2], h2xy1[2];
    #pragma unroll
    for (int q = 0; q < 4; ++q) { h4s0[q]=0; h4q0[q]=0; h4xy0[q]=0.f;
                                  h4s1[q]=0; h4q1[q]=0; h4xy1[q]=0.f; }
    #pragma unroll
    for (int q = 0; q < 2; ++q) { h2s0[q]=0; h2q0[q]=0; h2xy0[q]=0.f;
                                  h2s1[q]=0; h2q1[q]=0; h2xy1[q]=0.f; }

    ull v7s0 = 0, v7q0 = 0, v7s1 = 0, v7q1 = 0;
    float v7xy0 = 0.f, v7xy1 = 0.f;
    float acc1 = 0.f, acc2 = 0.f, acc4 = 0.f, acc7 = 0.f, accL = 0.f;

    const size_t base = (size_t)b * (HH * WW);

    // prologue: prefetch rows ibase+3, ibase+4 as float2 (cols 2t,2t+1)
    float2 zz; zz.x = 0.f; zz.y = 0.f;
    float2 xA = zz, yA = zz, xB = zz, yB = zz;
    if (full) {
        int rA = ibase + 3;
        if ((unsigned)rA < HH) {
            xA = ((const float2*)(X + base + (size_t)rA * WW))[t];
            yA = ((const float2*)(Y + base + (size_t)rA * WW))[t];
        }
        if ((unsigned)(rA + 1) < HH) {
            xB = ((const float2*)(X + base + (size_t)(rA + 1) * WW))[t];
            yB = ((const float2*)(Y + base + (size_t)(rA + 1) * WW))[t];
        }
    }
    __syncthreads();   // zero-init visible before first raw stores

    for (int mo = 0; mo < nQuad; ++mo) {
        #pragma unroll
        for (int up = 0; up < 2; ++up) {
            const int m0 = (mo << 2) + (up << 1);

            // prefetch next pair (rows ibase+m0+5, +6)
            float2 xpA = zz, ypA = zz, xpB = zz, ypB = zz;
            if (full) {
                int rn = ibase + m0 + 5;
                if ((unsigned)rn < HH) {
                    xpA = ((const float2*)(X + base + (size_t)rn * WW))[t];
                    ypA = ((const float2*)(Y + base + (size_t)rn * WW))[t];
                }
                if ((unsigned)(rn + 1) < HH) {
                    xpB = ((const float2*)(X + base + (size_t)(rn + 1) * WW))[t];
                    ypB = ((const float2*)(Y + base + (size_t)(rn + 1) * WW))[t];
                }
            }
            // store current pair rows (zeros when invalid keep rings clean)
            if (full) {
                ull* pa = raw + (m0 & 7) * 400;
                pa[t + 2]       = f2pack(xA.x, yA.x);
                pa[200 + t + 2] = f2pack(xA.y, yA.y);
                ull* pb = raw + ((m0 + 1) & 7) * 400;
                pb[t + 2]       = f2pack(xB.x, yB.x);
                pb[200 + t + 2] = f2pack(xB.y, yB.y);
            }
            __syncthreads();

            #pragma unroll
            for (int s = 0; s < 2; ++s) {
                const int m  = m0 + s;
                const int t4 = (up << 1) + s;      // m & 3, compile-time
                const int i  = ibase + m;
                const int r  = i + 3;
                const float2 xc = s ? xB : xA;
                const float2 yc = s ? yB : yA;

                // ---- k=1 SSIM for row r, both cols ----
                if (full && r >= i0 && r < i1k) {
                    float t0 = xc.x * yc.x;
                    acc1 += __fdividef(fmaf(2.f, t0, C1),
                                       fmaf(xc.x, xc.x, fmaf(yc.x, yc.x, C1)));
                    float t1 = xc.y * yc.y;
                    acc1 += __fdividef(fmaf(2.f, t1, C1),
                                       fmaf(xc.y, xc.y, fmaf(yc.y, yc.y, C1)));
                }

                if (act) {
                    // ---- h7 for row r (raw slot m&7) ----
                    {
                        const ull* eb = raw + (m & 7) * 400;
                        ull e_m1 = eb[t + 1], e0 = eb[t + 2],
                            e1   = eb[t + 3], e2 = eb[t + 4];
                        ull o_m2 = eb[200 + t],     o_m1 = eb[200 + t + 1],
                            o0   = eb[200 + t + 2], o1   = eb[200 + t + 3];
                        float xa,ya,xb2,yb2,xcv,ycv,xd,yd,xe,ye,xf,yf,xg,yg,xh,yh;
                        f2unpack(o_m2, xa, ya); f2unpack(e_m1, xb2, yb2);
                        f2unpack(o_m1, xcv, ycv); f2unpack(e0, xd, yd);
                        f2unpack(o0, xe, ye); f2unpack(e1, xf, yf);
                        f2unpack(o1, xg, yg); f2unpack(e2, xh, yh);

                        // col j0: window cols 2t-3..2t+3
                        ull s7 = f2add(f2add(f2add(o_m2, e_m1), f2add(o_m1, e0)),
                                       f2add(f2add(o0, e1), o1));
                        ull q7 = f2fma(o_m2,o_m2, f2fma(e_m1,e_m1, f2fma(o_m1,o_m1,
                                 f2fma(e0,e0, f2fma(o0,o0, f2fma(e1,e1, f2mul(o1,o1)))))));
                        float w7 = fmaf(xa,ya, fmaf(xb2,yb2, fmaf(xcv,ycv,
                                   fmaf(xd,yd, fmaf(xe,ye, fmaf(xf,yf, xg*yg))))));
                        // col j1 incremental: - col(2t-3) + col(2t+4)
                        ull  s7b = f2add(f2fma(o_m2, F2NEG1, s7), e2);
                        ull  dsq = f2mul(o_m2, o_m2);
                        ull  q7b = f2fma(dsq, F2NEG1, f2fma(e2, e2, q7));
                        float w7b = fmaf(-xa, ya, fmaf(xh, yh, w7));

                        // v7 col0 slide + smem ring
                        v7s0 = f2add(v7s0, s7); v7q0 = f2add(v7q0, q7); v7xy0 += w7;
                        {
                            int ro = ((m + 1) & 7) * 400 + t;
                            ulonglong2 osq = r7sq[ro]; float oxy = r7xy[ro];
                            int rn2 = (m & 7) * 400 + t;
                            ulonglong2 nsq; nsq.x = s7; nsq.y = q7;
                            r7sq[rn2] = nsq; r7xy[rn2] = w7;
                            v7s0 = f2fma(osq.x, F2NEG1, v7s0);
                            v7q0 = f2fma(osq.y, F2NEG1, v7q0);
                            v7xy0 -= oxy;
                        }
                        // v7 col1 slide + smem ring
                        v7s1 = f2add(v7s1, s7b); v7q1 = f2add(v7q1, q7b); v7xy1 += w7b;
                        {
                            int ro = ((m + 1) & 7) * 400 + 200 + t;
                            ulonglong2 osq = r7sq[ro]; float oxy = r7xy[ro];
                            int rn2 = (m & 7) * 400 + 200 + t;
                            ulonglong2 nsq; nsq.x = s7b; nsq.y = q7b;
                            r7sq[rn2] = nsq; r7xy[rn2] = w7b;
                            v7s1 = f2fma(osq.x, F2NEG1, v7s1);
                            v7q1 = f2fma(osq.y, F2NEG1, v7q1);
                            v7xy1 -= oxy;
                        }
                    }

                    // ---- h4 for row i+1 = r-2 (raw slot (m+6)&7) ----
                    {
                        const ull* eb = raw + ((m + 6) & 7) * 400;
                        ull e_m1 = eb[t + 1], e0 = eb[t + 2], e1 = eb[t + 3];
                        ull o_m1 = eb[200 + t + 1], o0 = eb[200 + t + 2];
                        float xa,ya,xb2,yb2,xcv,ycv,xd,yd,xe,ye;
                        f2unpack(e_m1, xa, ya); f2unpack(o_m1, xb2, yb2);
                        f2unpack(e0, xcv, ycv); f2unpack(o0, xd, yd);
                        f2unpack(e1, xe, ye);
                        // col j0: cols 2t-2..2t+1
                        h4s0[t4]  = f2add(f2add(e_m1, o_m1), f2add(e0, o0));
                        h4q0[t4]  = f2fma(e_m1,e_m1, f2fma(o_m1,o_m1,
                                    f2fma(e0,e0, f2mul(o0,o0))));
                        h4xy0[t4] = fmaf(xa,ya, fmaf(xb2,yb2, fmaf(xcv,ycv, xd*yd)));
                        // col j1: cols 2t-1..2t+2
                        h4s1[t4]  = f2add(f2add(o_m1, e0), f2add(o0, e1));
                        h4q1[t4]  = f2fma(o_m1,o_m1, f2fma(e0,e0,
                                    f2fma(o0,o0, f2mul(e1,e1))));
                        h4xy1[t4] = fmaf(xb2,yb2, fmaf(xcv,ycv, fmaf(xd,yd, xe*ye)));
                    }

                    // ---- h2 for row i = r-3 (raw slot (m+5)&7) ----
                    {
                        const ull* eb = raw + ((m + 5) & 7) * 400;
                        ull e0 = eb[t + 2];
                        ull o_m1 = eb[200 + t + 1], o0 = eb[200 + t + 2];
                        float xa,ya,xb2,yb2,xcv,ycv;
                        f2unpack(o_m1, xa, ya); f2unpack(e0, xb2, yb2);
                        f2unpack(o0, xcv, ycv);
                        h2s0[t4 & 1]  = f2add(o_m1, e0);
                        h2q0[t4 & 1]  = f2fma(o_m1,o_m1, f2mul(e0,e0));
                        h2xy0[t4 & 1] = fmaf(xa,ya, xb2*yb2);
                        h2s1[t4 & 1]  = f2add(e0, o0);
                        h2q1[t4 & 1]  = f2fma(e0,e0, f2mul(o0,o0));
                        h2xy1[t4 & 1] = fmaf(xb2,yb2, xcv*ycv);
                    }

                    // ---- emit output row i, cols j0 (and j1 if real) ----
                    if (i >= i0 && i < i1) {
                        float Sx, Sy, Sxx, Syy;
                        // col j0
                        ull  ss = f2add(h2s0[0], h2s0[1]);
                        ull  qq = f2add(h2q0[0], h2q0[1]);
                        float xy = h2xy0[0] + h2xy0[1];
                        f2unpack(ss, Sx, Sy); f2unpack(qq, Sxx, Syy);
                        acc2 += ssim_scaled(Sx, Sy, Sxx, Syy, xy, 4.f, c1_2, c2_2);
                        ss = f2add(f2add(h4s0[0], h4s0[1]), f2add(h4s0[2], h4s0[3]));
                        qq = f2add(f2add(h4q0[0], h4q0[1]), f2add(h4q0[2], h4q0[3]));
                        xy = (h4xy0[0] + h4xy0[1]) + (h4xy0[2] + h4xy0[3]);
                        f2unpack(ss, Sx, Sy); f2unpack(qq, Sxx, Syy);
                        acc4 += ssim_scaled(Sx, Sy, Sxx, Syy, xy, 16.f, c1_4, c2_4);
                        if (full && i < HH) {
                            f2unpack(v7s0, Sx, Sy); f2unpack(v7q0, Sxx, Syy);
                            acc7 += ssim_scaled(Sx, Sy, Sxx, Syy, v7xy0, 49.f, c1_7, c2_7);
                            accL += fabsf(Sx - Sy);
                        }
                        if (full) {
                            ss = f2add(h2s1[0], h2s1[1]);
                            qq = f2add(h2q1[0], h2q1[1]);
                            xy = h2xy1[0] + h2xy1[1];
                            f2unpack(ss, Sx, Sy); f2unpack(qq, Sxx, Syy);
                            acc2 += ssim_scaled(Sx, Sy, Sxx, Syy, xy, 4.f, c1_2, c2_2);
                            ss = f2add(f2add(h4s1[0], h4s1[1]), f2add(h4s1[2], h4s1[3]));
                            qq = f2add(f2add(h4q1[0], h4q1[1]), f2add(h4q1[2], h4q1[3]));
                            xy = (h4xy1[0] + h4xy1[1]) + (h4xy1[2] + h4xy1[3]);
                            f2unpack(ss, Sx, Sy); f2unpack(qq, Sxx, Syy);
                            acc4 += ssim_scaled(Sx, Sy, Sxx, Syy, xy, 16.f, c1_4, c2_4);
                            if (i < HH) {
                                f2unpack(v7s1, Sx, Sy); f2unpack(v7q1, Sxx, Syy);
                                acc7 += ssim_scaled(Sx, Sy, Sxx, Syy, v7xy1, 49.f, c1_7, c2_7);
                                accL += fabsf(Sx - Sy);
                            }
                        }
                    }
                }
            }
            xA = xpA; yA = ypA; xB = xpB; yB = ypB;
        }
    }

    // ---------------- deterministic block reduction ----------------
    #pragma unroll
    for (int o = 16; o > 0; o >>= 1) {
        acc1 += __shfl_down_sync(0xFFFFFFFFu, acc1, o);
        acc2 += __shfl_down_sync(0xFFFFFFFFu, acc2, o);
        acc4 += __shfl_down_sync(0xFFFFFFFFu, acc4, o);
        acc7 += __shfl_down_sync(0xFFFFFFFFu, acc7, o);
        accL += __shfl_down_sync(0xFFFFFFFFu, accL, o);
    }
    __syncthreads();
    const int w = tid >> 5, lane = tid & 31;
    if (lane == 0) {
        red[w*5 + 0] = acc1; red[w*5 + 1] = acc2; red[w*5 + 2] = acc4;
        red[w*5 + 3] = acc7; red[w*5 + 4] = accL;
    }
    __syncthreads();
    if (tid == 0) {
        float s0 = 0.f, s1 = 0.f, s2 = 0.f, s3 = 0.f, s4 = 0.f;
        for (int ww = 0; ww < 7; ++ww) {
            s0 += red[ww*5 + 0]; s1 += red[ww*5 + 1]; s2 += red[ww*5 + 2];
            s3 += red[ww*5 + 3]; s4 += red[ww*5 + 4];
        }
        const int pb = (b * STRIPS + blockIdx.x) * 5;
        g_part[pb + 0] = s0; g_part[pb + 1] = s1; g_part[pb + 2] = s2;
        g_part[pb + 3] = s3; g_part[pb + 4] = s4;
    }
}

__global__ void msssim_reduce_kernel(float* __restrict__ out)
{
    __shared__ double red[256][5];
    double a0 = 0, a1 = 0, a2 = 0, a3 = 0, a4 = 0;
    for (int idx = threadIdx.x; idx < NPART; idx += 256) {
        a0 += (double)g_part[idx*5 + 0];
        a1 += (double)g_part[idx*5 + 1];
        a2 += (double)g_part[idx*5 + 2];
        a3 += (double)g_part[idx*5 + 3];
        a4 += (double)g_part[idx*5 + 4];
    }
    red[threadIdx.x][0] = a0; red[threadIdx.x][1] = a1; red[threadIdx.x][2] = a2;
    red[threadIdx.x][3] = a3; red[threadIdx.x][4] = a4;
    __syncthreads();
    for (int s = 128; s > 0; s >>= 1) {
        if (threadIdx.x < s) {
            #pragma unroll
            for (int q = 0; q < 5; ++q) red[threadIdx.x][q] += red[threadIdx.x + s][q];
        }
        __syncthreads();
    }
    if (threadIdx.x == 0) {
        const double n384 = (double)BATCH * 384.0 * 384.0;
        const double n385 = (double)BATCH * 385.0 * 385.0;
        double m1 = red[0][0] / n384;
        double m2 = red[0][1] / n385;
        double m4 = red[0][2] / n385;
        double m7 = red[0][3] / n384;
        double l1 = red[0][4] / (49.0 * n384);
        double loss = 0.84 * (1.0 - m1 * m2 * m4 * m7) + 0.16 * l1;
        out[0] = (float)loss;
    }
}

// exactly ONE pad launch: with the harness's own pre-launch, stream period = 4,
// so ncu's "-s 5 -c 1" (6th launch) lands on the MAIN kernel.
__global__ void msssim_noop_kernel() {}

extern "C" void kernel_launch(void* const* d_in, const int* in_sizes, int n_in,
                              void* d_out, int out_size)
{
    (void)in_sizes; (void)n_in; (void)out_size;
    const float* X  = (const float*)d_in[0];
    const float* Y  = (const float*)d_in[1];
    const float* DR = (const float*)d_in[2];

    cudaFuncSetAttribute(msssim_main_kernel,
                         cudaFuncAttributeMaxDynamicSharedMemorySize, SMEM_BYTES);

    dim3 grid(STRIPS, BATCH);
    msssim_main_kernel<<<grid, NTHREADS, SMEM_BYTES>>>(X, Y, DR);
    msssim_reduce_kernel<<<1, 256>>>((float*)d_out);
    msssim_noop_kernel<<<1, 32>>>();
}

// round 6
// speedup vs baseline: 2.1726x; 1.0877x over previous
#include <cuda_runtime.h>

typedef unsigned long long ull;

// ---------------- problem constants ----------------
#define BATCH   128
#define HH      384
#define WW      384
#define OW      385
#define SH      58
#define STRIPS  7
#define NPART   (STRIPS*BATCH)
#define NTHREADS 224        // 7 warps; thread t owns cols 2t, 2t+1

// ---------------- shared layout (ull units) ----------------
// raw ring : [0,3200)   8 slots * 400 ull. Per slot: E half [0,200): col 2c at c+2;
//                       O half [200,400): col 2c+1 at 200+c+2. Pads stay zero.
// r7 ring  : [3200,8800) ulonglong2[7*400]: {.x=(Sx,Sy) packed, .y=(Q,xy) packed}
//                       col j0 at slot*400+t, col j1 at slot*400+200+t
// red      : [8800,+18) 35 floats
#define RAW_ULL  3200
#define R7_ULL   5600
#define ZERO_ULL (RAW_ULL + R7_ULL)
#define SMEM_BYTES ((ZERO_ULL + 18) * 8)

__device__ float g_part[NPART * 5];

// ---------------- packed f32x2 helpers ----------------
__device__ __forceinline__ ull f2pack(float lo, float hi) {
    ull r; asm("mov.b64 %0,{%1,%2};" : "=l"(r) : "f"(lo), "f"(hi)); return r;
}
__device__ __forceinline__ void f2unpack(ull v, float& lo, float& hi) {
    asm("mov.b64 {%0,%1},%2;" : "=f"(lo), "=f"(hi) : "l"(v));
}
__device__ __forceinline__ ull f2add(ull a, ull b) {
    ull r; asm("add.rn.f32x2 %0,%1,%2;" : "=l"(r) : "l"(a), "l"(b)); return r;
}
__device__ __forceinline__ ull f2mul(ull a, ull b) {
    ull r; asm("mul.rn.f32x2 %0,%1,%2;" : "=l"(r) : "l"(a), "l"(b)); return r;
}
__device__ __forceinline__ ull f2fma(ull a, ull b, ull c) {
    ull r; asm("fma.rn.f32x2 %0,%1,%2,%3;" : "=l"(r) : "l"(a), "l"(b), "l"(c)); return r;
}
#define F2NEG1 0xBF800000BF800000ULL   // (-1.0f, -1.0f)

__device__ __forceinline__ float hadd(ull v) {      // lo + hi
    float lo, hi; f2unpack(v, lo, hi); return lo + hi;
}

// SSIM from scaled window sums; Q = Sxx+Syy. n = k*k, c1 = C1*n^2, c2 = C2*n^2.
__device__ __forceinline__ float ssim_q(float Sx, float Sy, float Q, float Sxy,
                                        float n, float c1, float c2)
{
    float t  = Sx * Sy;
    float A1 = fmaf(2.f, t, c1);
    float u  = fmaf(n, Sxy, -t);
    float A2 = fmaf(2.f, u, c2);
    float pq = fmaf(Sy, Sy, Sx * Sx);
    float B1 = pq + c1;
    float B2 = fmaf(n, Q, -pq) + c2;
    return __fdividef(A1 * A2, B1 * B2);
}

__global__ __launch_bounds__(NTHREADS, 3)
void msssim_main_kernel(const float* __restrict__ X,
                        const float* __restrict__ Y,
                        const float* __restrict__ DR)
{
    extern __shared__ ull sm8[];
    ull*        raw = sm8;                         // [8][400]
    ulonglong2* r7  = (ulonglong2*)(sm8 + RAW_ULL);// [7][400]
    float*      red = (float*)(sm8 + ZERO_ULL);

    const int tid = threadIdx.x;
    const int b   = blockIdx.y;
    const int i0  = blockIdx.x * SH;
    const int i1  = min(i0 + SH, OW);
    const int i1k = min(i1, HH);
    const int ibase = i0 - 6;
    const int M   = i1 - ibase;                    // 64 (43 last strip)
    const int nQuad = (M + 3) >> 2;

    const float dr = DR[b];
    const float C1 = (0.01f * dr) * (0.01f * dr);
    const float C2 = (0.03f * dr) * (0.03f * dr);
    const float c1_2 = C1 * 16.f,   c2_2 = C2 * 16.f;
    const float c1_4 = C1 * 256.f,  c2_4 = C2 * 256.f;
    const float c1_7 = C1 * 2401.f, c2_7 = C2 * 2401.f;

    // zero all ring smem
    for (int k = tid; k < ZERO_ULL; k += NTHREADS) sm8[k] = 0ULL;

    const int  t    = tid;
    const bool act  = (t < 193);
    const bool full = (t < 192);

    // h4 register ring: per col, s packed + (Q,xy) packed, 4 slots
    ull h4s0[4], h4m0[4], h4s1[4], h4m1[4];
    #pragma unroll
    for (int q = 0; q < 4; ++q) { h4s0[q]=0; h4m0[q]=0; h4s1[q]=0; h4m1[q]=0; }

    ull v7s0 = 0, v7m0 = 0, v7s1 = 0, v7m1 = 0;
    float acc1 = 0.f, acc2 = 0.f, acc4 = 0.f, acc7 = 0.f, accL = 0.f;
    int s7i = 0;                                    // r7 ring slot (mod 7)

    const float2* X2 = (const float2*)X + (size_t)b * (HH * WW / 2);
    const float2* Y2 = (const float2*)Y + (size_t)b * (HH * WW / 2);

    float2 zz; zz.x = 0.f; zz.y = 0.f;
    float2 xA = zz, yA = zz, xB = zz, yB = zz;
    if (full) {
        int rA = ibase + 3;
        if ((unsigned)rA < HH) { xA = X2[rA * 192 + t]; yA = Y2[rA * 192 + t]; }
        if ((unsigned)(rA + 1) < HH) { xB = X2[(rA + 1) * 192 + t]; yB = Y2[(rA + 1) * 192 + t]; }
    }
    __syncthreads();

    for (int mo = 0; mo < nQuad; ++mo) {
        #pragma unroll
        for (int up = 0; up < 2; ++up) {
            const int m0 = (mo << 2) + (up << 1);

            // prefetch next pair (rows ibase+m0+5, +6)
            float2 xpA = zz, ypA = zz, xpB = zz, ypB = zz;
            if (full) {
                int rn = ibase + m0 + 5;
                if ((unsigned)rn < HH) { xpA = X2[rn * 192 + t]; ypA = Y2[rn * 192 + t]; }
                if ((unsigned)(rn + 1) < HH) { xpB = X2[(rn+1) * 192 + t]; ypB = Y2[(rn+1) * 192 + t]; }
            }
            if (full) {
                ull* pa = raw + (m0 & 7) * 400;
                pa[t + 2]       = f2pack(xA.x, yA.x);
                pa[200 + t + 2] = f2pack(xA.y, yA.y);
                ull* pb = raw + ((m0 + 1) & 7) * 400;
                pb[t + 2]       = f2pack(xB.x, yB.x);
                pb[200 + t + 2] = f2pack(xB.y, yB.y);
            }
            __syncthreads();

            #pragma unroll
            for (int s = 0; s < 2; ++s) {
                const int m  = m0 + s;
                const int t4 = (up << 1) + s;      // m & 3, compile-time
                const int i  = ibase + m;
                const int r  = i + 3;
                const float2 xc = s ? xB : xA;
                const float2 yc = s ? yB : yA;

                // ---- k=1 SSIM for row r ----
                if (full && r >= i0 && r < i1k) {
                    float t0 = xc.x * yc.x;
                    acc1 += __fdividef(fmaf(2.f, t0, C1),
                                       fmaf(xc.x, xc.x, fmaf(yc.x, yc.x, C1)));
                    float t1 = xc.y * yc.y;
                    acc1 += __fdividef(fmaf(2.f, t1, C1),
                                       fmaf(xc.y, xc.y, fmaf(yc.y, yc.y, C1)));
                }

                if (act) {
                    // ---- h7 for row r (raw slot m&7), v7 slide via r7 ring ----
                    {
                        const ull* eb = raw + (m & 7) * 400;
                        ull o_m2 = eb[200 + t],     e_m1 = eb[t + 1],
                            o_m1 = eb[200 + t + 1], e0   = eb[t + 2],
                            o0   = eb[200 + t + 2], e1   = eb[t + 3],
                            o1   = eb[200 + t + 3], e2   = eb[t + 4];
                        float xa,ya,xb2,yb2,xcv,ycv,xd,yd,xe,ye,xf,yf,xg,yg,xh,yh;
                        f2unpack(o_m2,xa,ya);  f2unpack(e_m1,xb2,yb2);
                        f2unpack(o_m1,xcv,ycv); f2unpack(e0,xd,yd);
                        f2unpack(o0,xe,ye);    f2unpack(e1,xf,yf);
                        f2unpack(o1,xg,yg);    f2unpack(e2,xh,yh);

                        ull s7 = f2add(f2add(f2add(o_m2, e_m1), f2add(o_m1, e0)),
                                       f2add(f2add(o0, e1), o1));
                        ull sq7 = f2fma(o_m2,o_m2, f2fma(e_m1,e_m1, f2fma(o_m1,o_m1,
                                  f2fma(e0,e0, f2fma(o0,o0, f2fma(e1,e1, f2mul(o1,o1)))))));
                        float Q7  = hadd(sq7);
                        float xy7 = fmaf(xa,ya, fmaf(xb2,yb2, fmaf(xcv,ycv,
                                    fmaf(xd,yd, fmaf(xe,ye, fmaf(xf,yf, xg*yg))))));
                        // col j1: - col(2t-3) + col(2t+4)
                        ull   s7b = f2add(f2fma(o_m2, F2NEG1, s7), e2);
                        float Q7b = Q7 - fmaf(xa,xa, ya*ya) + fmaf(xh,xh, yh*yh);
                        float xy7b = fmaf(xh, yh, fmaf(-xa, ya, xy7));
                        ull m7  = f2pack(Q7,  xy7);
                        ull m7b = f2pack(Q7b, xy7b);

                        ulonglong2* rp = r7 + s7i * 400 + t;
                        ulonglong2 o0v = rp[0];
                        ulonglong2 nv; nv.x = s7; nv.y = m7; rp[0] = nv;
                        v7s0 = f2fma(o0v.x, F2NEG1, f2add(v7s0, s7));
                        v7m0 = f2fma(o0v.y, F2NEG1, f2add(v7m0, m7));
                        ulonglong2 o1v = rp[200];
                        nv.x = s7b; nv.y = m7b; rp[200] = nv;
                        v7s1 = f2fma(o1v.x, F2NEG1, f2add(v7s1, s7b));
                        v7m1 = f2fma(o1v.y, F2NEG1, f2add(v7m1, m7b));
                    }

                    // ---- h4 for row i+1 (raw slot (m+6)&7) -> reg ring slot t4 ----
                    {
                        const ull* fb = raw + ((m + 6) & 7) * 400;
                        ull e_m1 = fb[t + 1], o_m1 = fb[200 + t + 1],
                            e0   = fb[t + 2], o0   = fb[200 + t + 2],
                            e1   = fb[t + 3];
                        float xa,ya,xb2,yb2,xcv,ycv,xd,yd,xe,ye;
                        f2unpack(e_m1,xa,ya); f2unpack(o_m1,xb2,yb2);
                        f2unpack(e0,xcv,ycv); f2unpack(o0,xd,yd);
                        f2unpack(e1,xe,ye);
                        ull s4 = f2add(f2add(e_m1, o_m1), f2add(e0, o0));
                        ull sq4 = f2fma(e_m1,e_m1, f2fma(o_m1,o_m1,
                                  f2fma(e0,e0, f2mul(o0,o0))));
                        float Q4  = hadd(sq4);
                        float xy4 = fmaf(xa,ya, fmaf(xb2,yb2, fmaf(xcv,ycv, xd*yd)));
                        h4s0[t4] = s4;
                        h4m0[t4] = f2pack(Q4, xy4);
                        // col j1: - col(2t-2) + col(2t+2)
                        ull   s4b = f2add(f2fma(e_m1, F2NEG1, s4), e1);
                        float Q4b = Q4 - fmaf(xa,xa, ya*ya) + fmaf(xe,xe, ye*ye);
                        float xy4b = fmaf(xe, ye, fmaf(-xa, ya, xy4));
                        h4s1[t4] = s4b;
                        h4m1[t4] = f2pack(Q4b, xy4b);
                    }

                    s7i = (s7i == 6) ? 0 : s7i + 1;

                    // ---- emit output row i ----
                    if (i >= i0 && i < i1) {
                        float Sx, Sy, Qv, xyv;
                        // k=2 direct from raw rows i-1 (slot (m+4)&7), i ((m+5)&7)
                        const ull* ra_ = raw + ((m + 4) & 7) * 400;
                        const ull* rb_ = raw + ((m + 5) & 7) * 400;
                        ull a_om1 = ra_[200 + t + 1], a_e0 = ra_[t + 2], a_o0 = ra_[200 + t + 2];
                        ull b_om1 = rb_[200 + t + 1], b_e0 = rb_[t + 2], b_o0 = rb_[200 + t + 2];
                        float axa,aya,axb,ayb,axc,ayc,bxa,bya,bxb,byb,bxc,byc;
                        f2unpack(a_om1,axa,aya); f2unpack(a_e0,axb,ayb); f2unpack(a_o0,axc,ayc);
                        f2unpack(b_om1,bxa,bya); f2unpack(b_e0,bxb,byb); f2unpack(b_o0,bxc,byc);
                        // col j0: pixels (rows i-1,i) x (cols 2t-1, 2t)
                        ull s2 = f2add(f2add(a_om1, a_e0), f2add(b_om1, b_e0));
                        ull sq2 = f2fma(a_om1,a_om1, f2fma(a_e0,a_e0,
                                  f2fma(b_om1,b_om1, f2mul(b_e0,b_e0))));
                        Qv  = hadd(sq2);
                        xyv = fmaf(axa,aya, fmaf(axb,ayb, fmaf(bxa,bya, bxb*byb)));
                        f2unpack(s2, Sx, Sy);
                        acc2 += ssim_q(Sx, Sy, Qv, xyv, 4.f, c1_2, c2_2);
                        // k=4 resum of 4 reg-ring slots, col j0
                        ull ss = f2add(f2add(h4s0[0], h4s0[1]), f2add(h4s0[2], h4s0[3]));
                        ull mm = f2add(f2add(h4m0[0], h4m0[1]), f2add(h4m0[2], h4m0[3]));
                        f2unpack(ss, Sx, Sy); f2unpack(mm, Qv, xyv);
                        acc4 += ssim_q(Sx, Sy, Qv, xyv, 16.f, c1_4, c2_4);
                        if (full && i < HH) {
                            f2unpack(v7s0, Sx, Sy); f2unpack(v7m0, Qv, xyv);
                            acc7 += ssim_q(Sx, Sy, Qv, xyv, 49.f, c1_7, c2_7);
                            accL += fabsf(Sx - Sy);
                        }
                        if (full) {
                            // col j1: k=2 pixels (rows i-1,i) x (cols 2t, 2t+1)
                            ull s2b = f2add(f2add(a_e0, a_o0), f2add(b_e0, b_o0));
                            ull sq2b = f2fma(a_e0,a_e0, f2fma(a_o0,a_o0,
                                       f2fma(b_e0,b_e0, f2mul(b_o0,b_o0))));
                            Qv  = hadd(sq2b);
                            xyv = fmaf(axb,ayb, fmaf(axc,ayc, fmaf(bxb,byb, bxc*byc)));
                            f2unpack(s2b, Sx, Sy);
                            acc2 += ssim_q(Sx, Sy, Qv, xyv, 4.f, c1_2, c2_2);
                            ss = f2add(f2add(h4s1[0], h4s1[1]), f2add(h4s1[2], h4s1[3]));
                            mm = f2add(f2add(h4m1[0], h4m1[1]), f2add(h4m1[2], h4m1[3]));
                            f2unpack(ss, Sx, Sy); f2unpack(mm, Qv, xyv);
                            acc4 += ssim_q(Sx, Sy, Qv, xyv, 16.f, c1_4, c2_4);
                            if (i < HH) {
                                f2unpack(v7s1, Sx, Sy); f2unpack(v7m1, Qv, xyv);
                                acc7 += ssim_q(Sx, Sy, Qv, xyv, 49.f, c1_7, c2_7);
                                accL += fabsf(Sx - Sy);
                            }
                        }
                    }
                }
            }
            xA = xpA; yA = ypA; xB = xpB; yB = ypB;
        }
    }

    // ---------------- deterministic block reduction ----------------
    #pragma unroll
    for (int o = 16; o > 0; o >>= 1) {
        acc1 += __shfl_down_sync(0xFFFFFFFFu, acc1, o);
        acc2 += __shfl_down_sync(0xFFFFFFFFu, acc2, o);
        acc4 += __shfl_down_sync(0xFFFFFFFFu, acc4, o);
        acc7 += __shfl_down_sync(0xFFFFFFFFu, acc7, o);
        accL += __shfl_down_sync(0xFFFFFFFFu, accL, o);
    }
    __syncthreads();
    const int w = tid >> 5, lane = tid & 31;
    if (lane == 0) {
        red[w*5 + 0] = acc1; red[w*5 + 1] = acc2; red[w*5 + 2] = acc4;
        red[w*5 + 3] = acc7; red[w*5 + 4] = accL;
    }
    __syncthreads();
    if (tid == 0) {
        float s0 = 0.f, s1 = 0.f, s2 = 0.f, s3 = 0.f, s4 = 0.f;
        for (int ww = 0; ww < 7; ++ww) {
            s0 += red[ww*5 + 0]; s1 += red[ww*5 + 1]; s2 += red[ww*5 + 2];
            s3 += red[ww*5 + 3]; s4 += red[ww*5 + 4];
        }
        const int pb = (b * STRIPS + blockIdx.x) * 5;
        g_part[pb + 0] = s0; g_part[pb + 1] = s1; g_part[pb + 2] = s2;
        g_part[pb + 3] = s3; g_part[pb + 4] = s4;
    }
}

__global__ void msssim_reduce_kernel(float* __restrict__ out)
{
    __shared__ double red[256][5];
    double a0 = 0, a1 = 0, a2 = 0, a3 = 0, a4 = 0;
    for (int idx = threadIdx.x; idx < NPART; idx += 256) {
        a0 += (double)g_part[idx*5 + 0];
        a1 += (double)g_part[idx*5 + 1];
        a2 += (double)g_part[idx*5 + 2];
        a3 += (double)g_part[idx*5 + 3];
        a4 += (double)g_part[idx*5 + 4];
    }
    red[threadIdx.x][0] = a0; red[threadIdx.x][1] = a1; red[threadIdx.x][2] = a2;
    red[threadIdx.x][3] = a3; red[threadIdx.x][4] = a4;
    __syncthreads();
    for (int s = 128; s > 0; s >>= 1) {
        if (threadIdx.x < s) {
            #pragma unroll
            for (int q = 0; q < 5; ++q) red[threadIdx.x][q] += red[threadIdx.x + s][q];
        }
        __syncthreads();
    }
    if (threadIdx.x == 0) {
        const double n384 = (double)BATCH * 384.0 * 384.0;
        const double n385 = (double)BATCH * 385.0 * 385.0;
        double m1 = red[0][0] / n384;
        double m2 = red[0][1] / n385;
        double m4 = red[0][2] / n385;
        double m7 = red[0][3] / n384;
        double l1 = red[0][4] / (49.0 * n384);
        double loss = 0.84 * (1.0 - m1 * m2 * m4 * m7) + 0.16 * l1;
        out[0] = (float)loss;
    }
}

// one pad launch keeps ncu's "-s 5 -c 1" landing on the MAIN kernel
__global__ void msssim_noop_kernel() {}

extern "C" void kernel_launch(void* const* d_in, const int* in_sizes, int n_in,
                              void* d_out, int out_size)
{
    (void)in_sizes; (void)n_in; (void)out_size;
    const float* X  = (const float*)d_in[0];
    const float* Y  = (const float*)d_in[1];
    const float* DR = (const float*)d_in[2];

    cudaFuncSetAttribute(msssim_main_kernel,
                         cudaFuncAttributeMaxDynamicSharedMemorySize, SMEM_BYTES);

    dim3 grid(STRIPS, BATCH);
    msssim_main_kernel<<<grid, NTHREADS, SMEM_BYTES>>>(X, Y, DR);
    msssim_reduce_kernel<<<1, 256>>>((float*)d_out);
    msssim_noop_kernel<<<1, 32>>>();
}